// round 2
// baseline (speedup 1.0000x reference)
#include <cuda_runtime.h>

// Problem shape (fixed by dataset): D=1024, P=256, R=64, K=1024
#define D_DIRS 1024
#define P_PTS  256
#define R_RANK 64
#define K_SUB  1024

#define GRID_FUSED 304   // 2 blocks per SM (152 SMs on GB300)

// Scratch (allocation-free rule: __device__ globals)
__device__ float g_M[R_RANK * R_RANK];  // M[r1][r2] = sum_d asum[d,r1]*bsum[d,r2]

// ---------------------------------------------------------------------------
// Fused kernel: for each assigned d, reduce atten/rad slabs over P (fully
// coalesced float4 streaming — this carries all 128 MiB of HBM traffic),
// then accumulate the rank-1 update asum_d (outer) bsum_d into a per-block
// register-resident 64x64 tile. One atomicAdd sweep per block at the end.
// Thread t owns r1 = t>>2, r2 in [(t&3)*16, (t&3)*16+16).
// ---------------------------------------------------------------------------
__global__ __launch_bounds__(256) void fused_reduce_m_kernel(
    const float* __restrict__ atten, const float* __restrict__ rad)
{
    const int t = threadIdx.x;
    __shared__ float4 s[256];
    __shared__ float asum[R_RANK];
    __shared__ float bsum[R_RANK];

    const int r1  = t >> 2;
    const int r2b = (t & 3) * 16;

    float macc[16];
    #pragma unroll
    for (int j = 0; j < 16; j++) macc[j] = 0.f;

    for (int d = blockIdx.x; d < D_DIRS; d += GRID_FUSED) {
        // ---- attenuation slab [P=256][R=64] = 4096 float4 ----
        {
            const float4* __restrict__ in =
                reinterpret_cast<const float4*>(atten) + (size_t)d * 4096;
            float4 acc = make_float4(0.f, 0.f, 0.f, 0.f);
            #pragma unroll
            for (int i = 0; i < 16; i++) {
                float4 v = in[i * 256 + t];
                acc.x += v.x; acc.y += v.y; acc.z += v.z; acc.w += v.w;
            }
            s[t] = acc;
            __syncthreads();
            if (t < 16) {
                float4 sum = s[t];
                #pragma unroll
                for (int j = 1; j < 16; j++) {
                    float4 v = s[j * 16 + t];
                    sum.x += v.x; sum.y += v.y; sum.z += v.z; sum.w += v.w;
                }
                reinterpret_cast<float4*>(asum)[t] = sum;
            }
            __syncthreads();
        }
        // ---- radiation slab ----
        {
            const float4* __restrict__ in =
                reinterpret_cast<const float4*>(rad) + (size_t)d * 4096;
            float4 acc = make_float4(0.f, 0.f, 0.f, 0.f);
            #pragma unroll
            for (int i = 0; i < 16; i++) {
                float4 v = in[i * 256 + t];
                acc.x += v.x; acc.y += v.y; acc.z += v.z; acc.w += v.w;
            }
            s[t] = acc;
            __syncthreads();
            if (t < 16) {
                float4 sum = s[t];
                #pragma unroll
                for (int j = 1; j < 16; j++) {
                    float4 v = s[j * 16 + t];
                    sum.x += v.x; sum.y += v.y; sum.z += v.z; sum.w += v.w;
                }
                reinterpret_cast<float4*>(bsum)[t] = sum;
            }
            __syncthreads();
        }
        // ---- rank-1 update into register tile ----
        {
            const float a = asum[r1];
            #pragma unroll
            for (int j = 0; j < 16; j++)
                macc[j] += a * bsum[r2b + j];
        }
        // asum/bsum are only rewritten after the next iteration's __syncthreads,
        // which each thread reaches only after finishing its reads above.
    }

    // accumulate into global M (g_M zeroed by a memset node each launch)
    #pragma unroll
    for (int j = 0; j < 16; j++)
        atomicAdd(&g_M[r1 * R_RANK + r2b + j], macc[j]);
}

// ---------------------------------------------------------------------------
// Quadform: csi[k] = (1/D) * f_k^T M f_k.
// 256 blocks x 256 threads; each block handles 4 k's (64 threads per k).
// M staged in smem with one coalesced 16 KB load.
// ---------------------------------------------------------------------------
__global__ __launch_bounds__(256) void quadform_kernel(
    const float* __restrict__ F, float* __restrict__ out)
{
    __shared__ float Msh[R_RANK * R_RANK];
    __shared__ float fsh[4][R_RANK];

    const int t = threadIdx.x;
    #pragma unroll
    for (int i = 0; i < 4; i++)
        reinterpret_cast<float4*>(Msh)[i * 256 + t] =
            reinterpret_cast<const float4*>(g_M)[i * 256 + t];

    const int klocal = t >> 6;   // 0..3
    const int r2 = t & 63;
    const int k = blockIdx.x * 4 + klocal;

    fsh[klocal][r2] = F[(size_t)k * R_RANK + r2];
    __syncthreads();

    float acc = 0.f;
    #pragma unroll
    for (int r1 = 0; r1 < R_RANK; r1++)
        acc += fsh[klocal][r1] * Msh[r1 * R_RANK + r2];
    float val = acc * fsh[klocal][r2];

    #pragma unroll
    for (int off = 16; off > 0; off >>= 1)
        val += __shfl_xor_sync(0xffffffffu, val, off);

    __shared__ float partial[8];
    if ((t & 31) == 0) partial[t >> 5] = val;
    __syncthreads();
    if (t < 4) {
        out[blockIdx.x * 4 + t] =
            (partial[2 * t] + partial[2 * t + 1]) * (1.0f / (float)D_DIRS);
    }
}

extern "C" void kernel_launch(void* const* d_in, const int* in_sizes, int n_in,
                              void* d_out, int out_size)
{
    const float* atten = (const float*)d_in[0];   // [D,P,R] fp32
    const float* rad   = (const float*)d_in[1];   // [D,P,R] fp32
    const float* F     = (const float*)d_in[2];   // [K,R]   fp32
    float* out = (float*)d_out;                   // [K]     fp32

    (void)in_sizes; (void)n_in; (void)out_size;

    // zero the accumulator (capturable memset node; no allocation)
    void* m_addr = nullptr;
    cudaGetSymbolAddress(&m_addr, g_M);
    cudaMemsetAsync(m_addr, 0, R_RANK * R_RANK * sizeof(float));

    fused_reduce_m_kernel<<<GRID_FUSED, 256>>>(atten, rad);
    quadform_kernel<<<K_SUB / 4, 256>>>(F, out);
}

// round 3
// speedup vs baseline: 1.2963x; 1.2963x over previous
#include <cuda_runtime.h>

// Problem shape (fixed by dataset): D=1024, P=256, R=64, K=1024
#define D_DIRS 1024
#define P_PTS  256
#define R_RANK 64
#define K_SUB  1024

// Scratch (allocation-free rule: __device__ globals)
__device__ float g_asum[D_DIRS * R_RANK];   // sum over p of attenuation
__device__ float g_bsum[D_DIRS * R_RANK];   // sum over p of radiation
__device__ float g_M[R_RANK * R_RANK];      // M[r1][r2] = sum_d asum[d,r1]*bsum[d,r2]

// ---------------------------------------------------------------------------
// Kernel 1: reduce over P.  One block per (tensor, d) — 2048 short-lived
// blocks, ~7 resident/SM, barrier-light: this is what sustains ~74% DRAM.
// Each block streams a contiguous 64 KB slab [P=256][R=64] with coalesced
// float4 loads (__ldcs: read-once, evict-first).
// ---------------------------------------------------------------------------
__global__ __launch_bounds__(256) void reduce_p_kernel(
    const float* __restrict__ atten, const float* __restrict__ rad)
{
    const int b = blockIdx.x;
    const bool is_b = (b >= D_DIRS);
    const int d = b & (D_DIRS - 1);
    const float* __restrict__ src = is_b ? rad : atten;
    float* __restrict__ dst = is_b ? g_bsum : g_asum;

    const float4* __restrict__ in =
        reinterpret_cast<const float4*>(src) + (size_t)d * (P_PTS * R_RANK / 4);

    const int t = threadIdx.x;

    float4 acc = make_float4(0.f, 0.f, 0.f, 0.f);
    #pragma unroll
    for (int i = 0; i < 16; i++) {
        float4 v = __ldcs(&in[i * 256 + t]);
        acc.x += v.x; acc.y += v.y; acc.z += v.z; acc.w += v.w;
    }

    __shared__ float4 s[256];
    s[t] = acc;
    __syncthreads();

    if (t < 16) {
        float4 sum = s[t];
        #pragma unroll
        for (int j = 1; j < 16; j++) {
            float4 v = s[j * 16 + t];
            sum.x += v.x; sum.y += v.y; sum.z += v.z; sum.w += v.w;
        }
        reinterpret_cast<float4*>(dst + d * R_RANK)[t] = sum;
    }
}

// ---------------------------------------------------------------------------
// Kernel 2: M += sum over a 16-d chunk of asum_d (outer) bsum_d.
// grid=64 blocks x 256 threads. Stage 16 rows of asum+bsum (8 KB) with one
// coalesced float4 load per thread per array; register tile 16 floats/thread
// (thread t owns r1=t>>2, r2 in [(t&3)*16, +16)); one atomicAdd sweep at end
// (64 blocks -> 64 adds per address, ~0.3us LTS tail). g_M zeroed by memset.
// ---------------------------------------------------------------------------
__global__ __launch_bounds__(256) void make_m_kernel()
{
    const int t = threadIdx.x;
    const int dbase = blockIdx.x * 16;

    __shared__ float sA[16 * R_RANK];
    __shared__ float sB[16 * R_RANK];

    // 16 d-rows x 64 floats = 1024 floats = 256 float4 per array
    reinterpret_cast<float4*>(sA)[t] =
        reinterpret_cast<const float4*>(g_asum + dbase * R_RANK)[t];
    reinterpret_cast<float4*>(sB)[t] =
        reinterpret_cast<const float4*>(g_bsum + dbase * R_RANK)[t];
    __syncthreads();

    const int r1  = t >> 2;
    const int r2b = (t & 3) * 16;

    float macc[16];
    #pragma unroll
    for (int j = 0; j < 16; j++) macc[j] = 0.f;

    #pragma unroll
    for (int i = 0; i < 16; i++) {
        const float a = sA[i * R_RANK + r1];
        #pragma unroll
        for (int j = 0; j < 16; j++)
            macc[j] += a * sB[i * R_RANK + r2b + j];
    }

    #pragma unroll
    for (int j = 0; j < 16; j++)
        atomicAdd(&g_M[r1 * R_RANK + r2b + j], macc[j]);
}

// ---------------------------------------------------------------------------
// Kernel 3: csi[k] = (1/D) * f_k^T M f_k.
// grid=128 x 256 threads: one warp per k (8 k's per block), lane owns r2 pair.
// M staged in smem once per block; f rows staged in smem (warp-broadcast LDS).
// ---------------------------------------------------------------------------
__global__ __launch_bounds__(256) void quadform_kernel(
    const float* __restrict__ F, float* __restrict__ out)
{
    __shared__ float Msh[R_RANK * R_RANK];   // 16 KB
    __shared__ float fsh[8][R_RANK];         // 2 KB

    const int t    = threadIdx.x;
    const int w    = t >> 5;      // warp = local k
    const int lane = t & 31;
    const int k    = blockIdx.x * 8 + w;

    // M: 4096 floats = 1024 float4 -> 4 per thread, coalesced
    #pragma unroll
    for (int i = 0; i < 4; i++)
        reinterpret_cast<float4*>(Msh)[i * 256 + t] =
            reinterpret_cast<const float4*>(g_M)[i * 256 + t];

    // F rows for this block's 8 k's: 512 floats = 128 float4
    if (t < 128)
        reinterpret_cast<float4*>(&fsh[0][0])[t] =
            reinterpret_cast<const float4*>(F + (size_t)blockIdx.x * 8 * R_RANK)[t];
    __syncthreads();

    // v[r2pair] = sum_r1 f[r1] * M[r1][r2pair]
    float2 acc = make_float2(0.f, 0.f);
    const float2* __restrict__ M2 = reinterpret_cast<const float2*>(Msh);
    #pragma unroll
    for (int r1 = 0; r1 < R_RANK; r1++) {
        const float fv = fsh[w][r1];          // warp-uniform broadcast
        const float2 m = M2[r1 * 32 + lane];
        acc.x += fv * m.x;
        acc.y += fv * m.y;
    }
    float val = acc.x * fsh[w][2 * lane] + acc.y * fsh[w][2 * lane + 1];

    #pragma unroll
    for (int off = 16; off > 0; off >>= 1)
        val += __shfl_xor_sync(0xffffffffu, val, off);

    if (lane == 0)
        out[k] = val * (1.0f / (float)D_DIRS);
}

extern "C" void kernel_launch(void* const* d_in, const int* in_sizes, int n_in,
                              void* d_out, int out_size)
{
    const float* atten = (const float*)d_in[0];   // [D,P,R] fp32
    const float* rad   = (const float*)d_in[1];   // [D,P,R] fp32
    const float* F     = (const float*)d_in[2];   // [K,R]   fp32
    float* out = (float*)d_out;                   // [K]     fp32

    (void)in_sizes; (void)n_in; (void)out_size;

    // zero the M accumulator (capturable memset node; no allocation)
    void* m_addr = nullptr;
    cudaGetSymbolAddress(&m_addr, g_M);
    cudaMemsetAsync(m_addr, 0, R_RANK * R_RANK * sizeof(float));

    reduce_p_kernel<<<2 * D_DIRS, 256>>>(atten, rad);
    make_m_kernel<<<D_DIRS / 16, 256>>>();
    quadform_kernel<<<K_SUB / 8, 256>>>(F, out);
}